// round 16
// baseline (speedup 1.0000x reference)
#include <cuda_runtime.h>
#include <cuda_bf16.h>
#include <cuda_fp16.h>
#include <cstdint>
#include <math.h>

// Problem constants
#define B_   2
#define N_   2048
#define DIN  2048
#define DOUT 2048
#define H_   32
#define KV_  8
#define DH_  64
#define M_   (B_ * N_)          // 4096
#define QKVW 3072               // fused Q|K|V output width

// -------- scratch (allocation-free rule: __device__ globals) --------
__device__ __align__(16) __half g_x16[(size_t)M_ * DIN];          // A for QKV gemm
__device__ __align__(16) __half g_Wqkv16[(size_t)QKVW * DIN];     // [n][k]
__device__ __align__(16) __half g_Wo16[(size_t)DIN * DOUT];       // [n][k]
__device__ __align__(16) __half g_QKV16[(size_t)M_ * QKVW];       // fused fp16 proj out
__device__ __align__(16) __half g_c16[(size_t)M_ * DOUT];         // ctx fp16

// ---------------- helpers ----------------
__device__ __forceinline__ unsigned h2u(float a, float b) {
    __half2 h = __floats2half2_rn(a, b);
    return *reinterpret_cast<unsigned*>(&h);
}
__device__ __forceinline__ float ex2(float x) {
    float r; asm("ex2.approx.ftz.f32 %0, %1;" : "=f"(r) : "f"(x)); return r;
}
// packed half2 exp2: one MUFU op for two values; returns fp16x2 A-frag word
__device__ __forceinline__ unsigned ex2h2(float a, float b) {
    unsigned d = h2u(a, b);
    unsigned r; asm("ex2.approx.f16x2 %0, %1;" : "=r"(r) : "r"(d));
    return r;
}
__device__ __forceinline__ void mma16f(float c[4], const unsigned a[4], const unsigned b[2]) {
    asm volatile(
        "mma.sync.aligned.m16n8k16.row.col.f32.f16.f16.f32 "
        "{%0,%1,%2,%3}, {%4,%5,%6,%7}, {%8,%9}, {%0,%1,%2,%3};"
        : "+f"(c[0]), "+f"(c[1]), "+f"(c[2]), "+f"(c[3])
        : "r"(a[0]), "r"(a[1]), "r"(a[2]), "r"(a[3]), "r"(b[0]), "r"(b[1]));
}
__device__ __forceinline__ unsigned smem_u32(const void* p) {
    unsigned a;
    asm("{ .reg .u64 t; cvta.to.shared.u64 t, %1; cvt.u32.u64 %0, t; }" : "=r"(a) : "l"(p));
    return a;
}
__device__ __forceinline__ void ldsm4(unsigned& r0, unsigned& r1, unsigned& r2, unsigned& r3,
                                      unsigned addr) {
    asm volatile("ldmatrix.sync.aligned.m8n8.x4.shared.b16 {%0,%1,%2,%3}, [%4];"
                 : "=r"(r0), "=r"(r1), "=r"(r2), "=r"(r3) : "r"(addr));
}
__device__ __forceinline__ void ldsm4t(unsigned& r0, unsigned& r1, unsigned& r2, unsigned& r3,
                                       unsigned addr) {
    asm volatile("ldmatrix.sync.aligned.m8n8.x4.trans.shared.b16 {%0,%1,%2,%3}, [%4];"
                 : "=r"(r0), "=r"(r1), "=r"(r2), "=r"(r3) : "r"(addr));
}
__device__ __forceinline__ void cpa16(unsigned saddr, const void* g) {
    asm volatile("cp.async.cg.shared.global [%0], [%1], 16;" :: "r"(saddr), "l"(g));
}

// ===================================================================
// Conversion kernels (inputs only)
// ===================================================================
__global__ __launch_bounds__(256)
void conv_x(const float4* __restrict__ src, uint2* __restrict__ dst)
{
    size_t i = (size_t)(blockIdx.x * 256 + threadIdx.x);
    float4 v = src[i];
    dst[i] = make_uint2(h2u(v.x, v.y), h2u(v.z, v.w));
}

// all four weight transposes in one launch (linear region map)
__global__ __launch_bounds__(256)
void tconv_all(const float* __restrict__ Wq, const float* __restrict__ Wk,
               const float* __restrict__ Wv, const float* __restrict__ Wo,
               __half* __restrict__ Wqkv16, __half* __restrict__ Wo16)
{
    int bid = blockIdx.x;
    const float* src; __half* dst; int K, N, row_off;
    if (bid < 4096)      { src = Wq; dst = Wqkv16; K = DIN;  N = 2048; row_off = 0; }
    else if (bid < 5120) { src = Wk; dst = Wqkv16; K = DIN;  N = 512;  row_off = 2048; bid -= 4096; }
    else if (bid < 6144) { src = Wv; dst = Wqkv16; K = DIN;  N = 512;  row_off = 2560; bid -= 5120; }
    else                 { src = Wo; dst = Wo16;   K = DOUT; N = DIN;  row_off = 0;    bid -= 6144; }
    int ntn = N / 32;
    int n0 = (bid % ntn) * 32, k0 = (bid / ntn) * 32;

    __shared__ float t[32][33];
    int tx = threadIdx.x & 31, ty = threadIdx.x >> 5;
#pragma unroll
    for (int i = 0; i < 4; i++)
        t[ty + i * 8][tx] = src[(size_t)(k0 + ty + i * 8) * N + n0 + tx];
    __syncthreads();
#pragma unroll
    for (int i = 0; i < 4; i++) {
        int n = ty + i * 8;
        dst[(size_t)(row_off + n0 + n) * K + k0 + tx] = __float2half_rn(t[tx][n]);
    }
}

// ===================================================================
// fp16 GEMM: C[M,Nc] = A[M,K] @ B^T. block 128x128, KT=64,
// 8 warps (2x4), cp.async 3-STAGE pipeline + ldmatrix.
// ===================================================================
#define GST 36
#define BUFW (128 * GST)
#define BUFB (BUFW * 4)
#define STAGEB (2 * BUFB)             // 36864 B per stage (A+B)
#define GEMM_SMEMB (3 * STAGEB)       // 110592 B

__global__ __launch_bounds__(256, 2)
void gemm_f16(const __half* __restrict__ Ag, const __half* __restrict__ Bg,
              float* __restrict__ Cf, __half* __restrict__ Ch,
              const float* __restrict__ bias,
              int Nc, int K, int scaleCols, float scaleVal)
{
    extern __shared__ unsigned smw[];
    const unsigned sb = smem_u32(smw);

    const int tid  = threadIdx.x;
    const int lane = tid & 31;
    const int wid  = tid >> 5;
    const int wr   = (wid >> 2) * 64;
    const int wc   = (wid & 3) * 32;
    const int brow = blockIdx.y * 128;
    const int bcol = blockIdx.x * 128;
    const int q    = lane & 3;
    const int l4   = lane >> 2;
    const int Kw   = K >> 1;
    const int sub  = lane >> 3;
    const int r8   = lane & 7;

    const unsigned* Aw = (const unsigned*)Ag;
    const unsigned* Bw = (const unsigned*)Bg;

    float acc[4][4][4];
#pragma unroll
    for (int i = 0; i < 4; i++)
#pragma unroll
        for (int j = 0; j < 4; j++)
#pragma unroll
            for (int e = 0; e < 4; e++) acc[i][j][e] = 0.0f;

    const int nst = K / 64;

    auto issue = [&](int stage, int kw0) {
        unsigned sd = sb + stage * STAGEB;
#pragma unroll
        for (int p = 0; p < 4; p++) {
            int id = tid + p * 256;
            int r  = id >> 3;
            int c4 = (id & 7) * 4;
            unsigned o = (unsigned)(r * GST + c4) * 4;
            cpa16(sd + o,        Aw + (size_t)(brow + r) * Kw + kw0 + c4);
            cpa16(sd + BUFB + o, Bw + (size_t)(bcol + r) * Kw + kw0 + c4);
        }
        asm volatile("cp.async.commit_group;");
    };

    issue(0, 0);
    issue(1, 32);

    for (int i = 0; i < nst; i++) {
        if (i + 2 < nst) {
            issue((i + 2) % 3, (i + 2) * 32);
            asm volatile("cp.async.wait_group 2;");
        } else if (i + 1 < nst) {
            asm volatile("cp.async.wait_group 1;");
        } else {
            asm volatile("cp.async.wait_group 0;");
        }
        __syncthreads();

        const unsigned sd = sb + (i % 3) * STAGEB;
        const unsigned sA = sd, sB = sd + BUFB;

#pragma unroll
        for (int ks2 = 0; ks2 < 32; ks2 += 8) {
            unsigned bh[4][2];
#pragma unroll
            for (int pr = 0; pr < 4; pr += 2) {
                int nrow = wc + (pr + (sub >> 1)) * 8 + r8;
                int colw = ks2 + (sub & 1) * 4;
                unsigned off = (unsigned)(nrow * GST + colw) * 4;
                ldsm4(bh[pr][0], bh[pr][1], bh[pr + 1][0], bh[pr + 1][1], sB + off);
            }
#pragma unroll
            for (int mt = 0; mt < 4; mt++) {
                int arow = wr + mt * 16 + (sub & 1) * 8 + r8;
                int colw = ks2 + (sub >> 1) * 4;
                unsigned off = (unsigned)(arow * GST + colw) * 4;
                unsigned ah[4];
                ldsm4(ah[0], ah[1], ah[2], ah[3], sA + off);
#pragma unroll
                for (int nt = 0; nt < 4; nt++)
                    mma16f(acc[mt][nt], ah, bh[nt]);
            }
        }
        __syncthreads();
    }

    if (Ch) {
        unsigned* Chw = (unsigned*)Ch;
        const int Ncw = Nc >> 1;
#pragma unroll
        for (int mt = 0; mt < 4; mt++) {
#pragma unroll
            for (int nt = 0; nt < 4; nt++) {
                int row = brow + wr + mt * 16 + l4;
                int col = bcol + wc + nt * 8 + 2 * q;
                float sc = (col < scaleCols) ? scaleVal : 1.0f;
                Chw[(size_t)row * Ncw + (col >> 1)] =
                    h2u(acc[mt][nt][0] * sc, acc[mt][nt][1] * sc);
                Chw[(size_t)(row + 8) * Ncw + (col >> 1)] =
                    h2u(acc[mt][nt][2] * sc, acc[mt][nt][3] * sc);
            }
        }
    } else {
#pragma unroll
        for (int mt = 0; mt < 4; mt++) {
#pragma unroll
            for (int nt = 0; nt < 4; nt++) {
                int row = brow + wr + mt * 16 + l4;
                int col = bcol + wc + nt * 8 + 2 * q;
                float b0 = 0.f, b1 = 0.f;
                if (bias) { b0 = bias[col]; b1 = bias[col + 1]; }
                *(float2*)(Cf + (size_t)row * Nc + col) =
                    make_float2(acc[mt][nt][0] + b0, acc[mt][nt][1] + b1);
                *(float2*)(Cf + (size_t)(row + 8) * Nc + col) =
                    make_float2(acc[mt][nt][2] + b0, acc[mt][nt][3] + b1);
            }
        }
    }
}

// ===================================================================
// Flash attention: FBM=128, FBN=64, 8 warps x 16 rows.
// cp.async double-buffered K/V tiles. P in registers. ldsm K/V frags.
// l via ones-MMA. Rescale skipped when no new max. Heavy-first blocks.
// exp2 via ex2.approx.f16x2 (2 values per MUFU op).
// ===================================================================
#define FBM 128
#define FBN 64
#define KSW 36                        // K/V row stride (words)
#define KBUF (FBN * KSW * 4)          // 9216 B per K (or V) buffer
#define FSTAGE (2 * KBUF)             // 18432 B per stage (K+V)
#define FLASH_SMEMB (2 * FSTAGE)      // 36864 B

__global__ __launch_bounds__(256, 2)
void flash16(const __half* __restrict__ QKV16, __half* __restrict__ c16)
{
    extern __shared__ char fsm[];
    const unsigned sbd = smem_u32(fsm);

    const int tid  = threadIdx.x;
    const int lane = tid & 31;
    const int wid  = tid >> 5;              // 0..7
    const int q    = lane & 3;
    const int l4   = lane >> 2;
    const int sub  = lane >> 3;
    const int r8   = lane & 7;
    // heavy-first: reverse q-tile order so long blocks start in wave 1
    const int m0   = (gridDim.x - 1 - blockIdx.x) * FBM;
    const int h    = blockIdx.y;
    const int b    = blockIdx.z;
    const int kv   = h >> 2;

    const int r0 = m0 + wid * 16 + l4;
    const int rowmin = m0 + wid * 16;
    const unsigned* W = (const unsigned*)QKV16;   // word ptr, row stride 1536

    // Q fragments (qscale pre-folded in gemm epilogue)
    unsigned qh[4][4];
    {
        size_t q0 = (size_t)(b * N_ + r0) * 1536 + h * 32;
        size_t q1 = q0 + (size_t)8 * 1536;
#pragma unroll
        for (int ks = 0; ks < 4; ks++) {
            qh[ks][0] = W[q0 + ks * 8 + q];
            qh[ks][1] = W[q1 + ks * 8 + q];
            qh[ks][2] = W[q0 + ks * 8 + q + 4];
            qh[ks][3] = W[q1 + ks * 8 + q + 4];
        }
    }

    float oacc[8][4];
#pragma unroll
    for (int d = 0; d < 8; d++)
#pragma unroll
        for (int e = 0; e < 4; e++) oacc[d][e] = 0.0f;
    float lacc[4] = {0.f, 0.f, 0.f, 0.f};       // row-sum C-frag (ones-MMA)
    float mcur0 = -1e30f, mcur1 = -1e30f;

    const unsigned ones2[2] = {0x3C003C00u, 0x3C003C00u};   // half2(1,1) x2

    const int rowmax = rowmin + 15;
    const int ntiles = (m0 + FBM) / FBN;

    auto fissue = [&](int stage, int n0) {
        unsigned sd = sbd + stage * FSTAGE;
#pragma unroll
        for (int p = 0; p < 2; p++) {
            int id = tid + p * 256;
            int r  = id >> 3;
            int w4 = (id & 7) * 4;
            size_t rowbase = (size_t)(b * N_ + n0 + r) * 1536 + kv * 32;
            unsigned o = (unsigned)(r * KSW + w4) * 4;
            cpa16(sd + o,        W + rowbase + 1024 + w4);   // K
            cpa16(sd + KBUF + o, W + rowbase + 1280 + w4);   // V
        }
        asm volatile("cp.async.commit_group;");
    };

    fissue(0, 0);

    for (int i = 0; i < ntiles; i++) {
        const int n0 = i * FBN;
        if (i + 1 < ntiles) {
            fissue((i + 1) & 1, n0 + FBN);
            asm volatile("cp.async.wait_group 1;");
        } else {
            asm volatile("cp.async.wait_group 0;");
        }
        __syncthreads();

        const unsigned sbK = sbd + (i & 1) * FSTAGE;
        const unsigned sbV = sbK + KBUF;

        if (n0 <= rowmax) {
            // ---- S = Q K^T : 4 k16 steps x 8 n-subtiles; ldsm interleaved ----
            float s[8][4];
#pragma unroll
            for (int nt = 0; nt < 8; nt++)
#pragma unroll
                for (int e = 0; e < 4; e++) s[nt][e] = 0.0f;

#pragma unroll
            for (int ks = 0; ks < 4; ks++) {
                const int colw = ks * 8 + (sub & 1) * 4;
#pragma unroll
                for (int pr = 0; pr < 8; pr += 2) {
                    int nrow = (pr + (sub >> 1)) * 8 + r8;
                    unsigned off = (unsigned)(nrow * KSW + colw) * 4;
                    unsigned b0[2], b1[2];
                    ldsm4(b0[0], b0[1], b1[0], b1[1], sbK + off);
                    mma16f(s[pr],     qh[ks], b0);
                    mma16f(s[pr + 1], qh[ks], b1);
                }
            }

            // ---- row max (mask only on diagonal tiles) ----
            float mt0 = -1e30f, mt1 = -1e30f;
            if (n0 + FBN - 1 > rowmin) {
#pragma unroll
                for (int nt = 0; nt < 8; nt++) {
#pragma unroll
                    for (int e = 0; e < 2; e++) {
                        int col = n0 + nt * 8 + 2 * q + e;
                        if (col > r0)     s[nt][e]     = -1e30f;
                        if (col > r0 + 8) s[nt][2 + e] = -1e30f;
                        mt0 = fmaxf(mt0, s[nt][e]);
                        mt1 = fmaxf(mt1, s[nt][2 + e]);
                    }
                }
            } else {
#pragma unroll
                for (int nt = 0; nt < 8; nt++) {
                    mt0 = fmaxf(mt0, fmaxf(s[nt][0], s[nt][1]));
                    mt1 = fmaxf(mt1, fmaxf(s[nt][2], s[nt][3]));
                }
            }
            mt0 = fmaxf(mt0, __shfl_xor_sync(0xffffffff, mt0, 1));
            mt0 = fmaxf(mt0, __shfl_xor_sync(0xffffffff, mt0, 2));
            mt1 = fmaxf(mt1, __shfl_xor_sync(0xffffffff, mt1, 1));
            mt1 = fmaxf(mt1, __shfl_xor_sync(0xffffffff, mt1, 2));

            float mn0 = fmaxf(mcur0, mt0);
            float mn1 = fmaxf(mcur1, mt1);
            // skip rescale when no lane saw a new max (cr==1 exactly)
            unsigned need = __ballot_sync(0xffffffff, (mn0 > mcur0) || (mn1 > mcur1));
            if (need) {
                float cr0 = ex2(mcur0 - mn0);
                float cr1 = ex2(mcur1 - mn1);
#pragma unroll
                for (int d = 0; d < 8; d++) {
                    oacc[d][0] *= cr0; oacc[d][1] *= cr0;
                    oacc[d][2] *= cr1; oacc[d][3] *= cr1;
                }
                lacc[0] *= cr0; lacc[1] *= cr0;
                lacc[2] *= cr1; lacc[3] *= cr1;
            }
            mcur0 = mn0; mcur1 = mn1;

            // ---- P via packed half2 exp2 (1 MUFU op per 2 values) ----
            unsigned pa[8][2];
#pragma unroll
            for (int nt = 0; nt < 8; nt++) {
                pa[nt][0] = ex2h2(s[nt][0] - mn0, s[nt][1] - mn0);
                pa[nt][1] = ex2h2(s[nt][2] - mn1, s[nt][3] - mn1);
            }

            // ---- O += P V ; l += P 1 : 4 k16 steps ----
#pragma unroll
            for (int ks = 0; ks < 4; ks++) {
                unsigned a[4];
                a[0] = pa[2 * ks][0];
                a[1] = pa[2 * ks][1];
                a[2] = pa[2 * ks + 1][0];
                a[3] = pa[2 * ks + 1][1];
                mma16f(lacc, a, ones2);                   // row sums
                int vrow = ks * 16 + (sub & 1) * 8 + r8;
#pragma unroll
                for (int dtp = 0; dtp < 4; dtp++) {
                    unsigned v0, v1, v2, v3;
                    unsigned addr = sbV + (unsigned)(vrow * (KSW * 4))
                                  + (unsigned)((dtp * 16 + (sub >> 1) * 8) * 2);
                    ldsm4t(v0, v1, v2, v3, addr);
                    unsigned b0[2] = {v0, v1};
                    unsigned b1[2] = {v2, v3};
                    mma16f(oacc[2 * dtp],     a, b0);
                    mma16f(oacc[2 * dtp + 1], a, b1);
                }
            }
        }
        __syncthreads();
    }

    // lacc columns are identical row sums — no reduction needed
    float inv0 = 1.0f / lacc[0];
    float inv1 = 1.0f / lacc[2];

    unsigned* cw = (unsigned*)c16;
    size_t c0 = (size_t)(b * N_ + r0) * 1024 + h * 32;
    size_t c1 = c0 + (size_t)8 * 1024;
#pragma unroll
    for (int dt = 0; dt < 8; dt++) {
        cw[c0 + dt * 4 + q] = h2u(oacc[dt][0] * inv0, oacc[dt][1] * inv0);
        cw[c1 + dt * 4 + q] = h2u(oacc[dt][2] * inv1, oacc[dt][3] * inv1);
    }
}

// ===================================================================
// Launch
// ===================================================================
extern "C" void kernel_launch(void* const* d_in, const int* in_sizes, int n_in,
                              void* d_out, int out_size)
{
    const float* x  = (const float*)d_in[0];
    const float* Wq = (const float*)d_in[1];
    const float* Wk = (const float*)d_in[2];
    const float* Wv = (const float*)d_in[3];
    const float* Wo = (const float*)d_in[4];
    const float* bo = (const float*)d_in[5];
    float* out = (float*)d_out;

    __half *x16, *Wqkv16, *Wo16, *QKV16, *c16;
    cudaGetSymbolAddress((void**)&x16,    g_x16);
    cudaGetSymbolAddress((void**)&Wqkv16, g_Wqkv16);
    cudaGetSymbolAddress((void**)&Wo16,   g_Wo16);
    cudaGetSymbolAddress((void**)&QKV16,  g_QKV16);
    cudaGetSymbolAddress((void**)&c16,    g_c16);

    cudaFuncSetAttribute(gemm_f16, cudaFuncAttributeMaxDynamicSharedMemorySize,
                         GEMM_SMEMB);
    cudaFuncSetAttribute(flash16, cudaFuncAttributeMaxDynamicSharedMemorySize,
                         FLASH_SMEMB);

    const float qscale = 0.125f * 1.44269504f;

    // input conversions
    conv_x<<<(int)((size_t)M_ * DIN / 4 / 256), 256>>>((const float4*)x, (uint2*)x16);
    tconv_all<<<10240, 256>>>(Wq, Wk, Wv, Wo, Wqkv16, Wo16);

    // fused QKV projection -> fp16 (Q columns pre-scaled by qscale)
    gemm_f16<<<dim3(QKVW / 128, M_ / 128), 256, GEMM_SMEMB>>>(
        x16, Wqkv16, nullptr, QKV16, nullptr, QKVW, DIN, 2048, qscale);

    // attention
    flash16<<<dim3(N_ / FBM, H_, B_), 256, FLASH_SMEMB>>>(QKV16, c16);

    // output projection + bias -> fp32 out
    gemm_f16<<<dim3(DIN / 128, M_ / 128), 256, GEMM_SMEMB>>>(
        c16, Wo16, out, nullptr, bo, DIN, DOUT, 0, 1.0f);
}

// round 17
// speedup vs baseline: 1.0088x; 1.0088x over previous
#include <cuda_runtime.h>
#include <cuda_bf16.h>
#include <cuda_fp16.h>
#include <cstdint>
#include <math.h>

// Problem constants
#define B_   2
#define N_   2048
#define DIN  2048
#define DOUT 2048
#define H_   32
#define KV_  8
#define DH_  64
#define M_   (B_ * N_)          // 4096
#define QKVW 3072               // fused Q|K|V output width

// -------- scratch (allocation-free rule: __device__ globals) --------
__device__ __align__(16) __half g_x16[(size_t)M_ * DIN];          // A for QKV gemm
__device__ __align__(16) __half g_Wqkv16[(size_t)QKVW * DIN];     // [n][k]
__device__ __align__(16) __half g_Wo16[(size_t)DIN * DOUT];       // [n][k]
__device__ __align__(16) __half g_QKV16[(size_t)M_ * QKVW];       // fused fp16 proj out
__device__ __align__(16) __half g_c16[(size_t)M_ * DOUT];         // ctx fp16

// ---------------- helpers ----------------
__device__ __forceinline__ unsigned h2u(float a, float b) {
    __half2 h = __floats2half2_rn(a, b);
    return *reinterpret_cast<unsigned*>(&h);
}
__device__ __forceinline__ float ex2(float x) {
    float r; asm("ex2.approx.ftz.f32 %0, %1;" : "=f"(r) : "f"(x)); return r;
}
__device__ __forceinline__ void mma16f(float c[4], const unsigned a[4], const unsigned b[2]) {
    asm volatile(
        "mma.sync.aligned.m16n8k16.row.col.f32.f16.f16.f32 "
        "{%0,%1,%2,%3}, {%4,%5,%6,%7}, {%8,%9}, {%0,%1,%2,%3};"
        : "+f"(c[0]), "+f"(c[1]), "+f"(c[2]), "+f"(c[3])
        : "r"(a[0]), "r"(a[1]), "r"(a[2]), "r"(a[3]), "r"(b[0]), "r"(b[1]));
}
__device__ __forceinline__ unsigned smem_u32(const void* p) {
    unsigned a;
    asm("{ .reg .u64 t; cvta.to.shared.u64 t, %1; cvt.u32.u64 %0, t; }" : "=r"(a) : "l"(p));
    return a;
}
__device__ __forceinline__ void ldsm4(unsigned& r0, unsigned& r1, unsigned& r2, unsigned& r3,
                                      unsigned addr) {
    asm volatile("ldmatrix.sync.aligned.m8n8.x4.shared.b16 {%0,%1,%2,%3}, [%4];"
                 : "=r"(r0), "=r"(r1), "=r"(r2), "=r"(r3) : "r"(addr));
}
__device__ __forceinline__ void ldsm4t(unsigned& r0, unsigned& r1, unsigned& r2, unsigned& r3,
                                       unsigned addr) {
    asm volatile("ldmatrix.sync.aligned.m8n8.x4.trans.shared.b16 {%0,%1,%2,%3}, [%4];"
                 : "=r"(r0), "=r"(r1), "=r"(r2), "=r"(r3) : "r"(addr));
}
__device__ __forceinline__ void cpa16(unsigned saddr, const void* g) {
    asm volatile("cp.async.cg.shared.global [%0], [%1], 16;" :: "r"(saddr), "l"(g));
}

// ===================================================================
// Conversion kernel: all weight transposes + x conversion, one launch
// ===================================================================
__global__ __launch_bounds__(256)
void conv_all(const float* __restrict__ x16src,
              const float* __restrict__ Wq, const float* __restrict__ Wk,
              const float* __restrict__ Wv, const float* __restrict__ Wo,
              __half* __restrict__ x16, __half* __restrict__ Wqkv16,
              __half* __restrict__ Wo16)
{
    int bid = blockIdx.x;
    if (bid >= 10240) {
        // x elementwise fp32 -> fp16 (8192 blocks)
        size_t i = (size_t)(bid - 10240) * 256 + threadIdx.x;
        float4 v = ((const float4*)x16src)[i];
        ((uint2*)x16)[i] = make_uint2(h2u(v.x, v.y), h2u(v.z, v.w));
        return;
    }
    const float* src; __half* dst; int K, N, row_off;
    if (bid < 4096)      { src = Wq; dst = Wqkv16; K = DIN;  N = 2048; row_off = 0; }
    else if (bid < 5120) { src = Wk; dst = Wqkv16; K = DIN;  N = 512;  row_off = 2048; bid -= 4096; }
    else if (bid < 6144) { src = Wv; dst = Wqkv16; K = DIN;  N = 512;  row_off = 2560; bid -= 5120; }
    else                 { src = Wo; dst = Wo16;   K = DOUT; N = DIN;  row_off = 0;    bid -= 6144; }
    int ntn = N / 32;
    int n0 = (bid % ntn) * 32, k0 = (bid / ntn) * 32;

    __shared__ float t[32][33];
    int tx = threadIdx.x & 31, ty = threadIdx.x >> 5;
#pragma unroll
    for (int i = 0; i < 4; i++)
        t[ty + i * 8][tx] = src[(size_t)(k0 + ty + i * 8) * N + n0 + tx];
    __syncthreads();
#pragma unroll
    for (int i = 0; i < 4; i++) {
        int n = ty + i * 8;
        dst[(size_t)(row_off + n0 + n) * K + k0 + tx] = __float2half_rn(t[tx][n]);
    }
}

// ===================================================================
// fp16 GEMM: C[M,Nc] = A[M,K] @ B^T. block 128x128, KT=64,
// 8 warps (2x4), cp.async 3-STAGE pipeline + ldmatrix.
// ===================================================================
#define GST 36
#define BUFW (128 * GST)
#define BUFB (BUFW * 4)
#define STAGEB (2 * BUFB)             // 36864 B per stage (A+B)
#define GEMM_SMEMB (3 * STAGEB)       // 110592 B

__global__ __launch_bounds__(256, 2)
void gemm_f16(const __half* __restrict__ Ag, const __half* __restrict__ Bg,
              float* __restrict__ Cf, __half* __restrict__ Ch,
              const float* __restrict__ bias,
              int Nc, int K, int scaleCols, float scaleVal)
{
    extern __shared__ unsigned smw[];
    const unsigned sb = smem_u32(smw);

    const int tid  = threadIdx.x;
    const int lane = tid & 31;
    const int wid  = tid >> 5;
    const int wr   = (wid >> 2) * 64;
    const int wc   = (wid & 3) * 32;
    const int brow = blockIdx.y * 128;
    const int bcol = blockIdx.x * 128;
    const int q    = lane & 3;
    const int l4   = lane >> 2;
    const int Kw   = K >> 1;
    const int sub  = lane >> 3;
    const int r8   = lane & 7;

    const unsigned* Aw = (const unsigned*)Ag;
    const unsigned* Bw = (const unsigned*)Bg;

    float acc[4][4][4];
#pragma unroll
    for (int i = 0; i < 4; i++)
#pragma unroll
        for (int j = 0; j < 4; j++)
#pragma unroll
            for (int e = 0; e < 4; e++) acc[i][j][e] = 0.0f;

    const int nst = K / 64;

    auto issue = [&](int stage, int kw0) {
        unsigned sd = sb + stage * STAGEB;
#pragma unroll
        for (int p = 0; p < 4; p++) {
            int id = tid + p * 256;
            int r  = id >> 3;
            int c4 = (id & 7) * 4;
            unsigned o = (unsigned)(r * GST + c4) * 4;
            cpa16(sd + o,        Aw + (size_t)(brow + r) * Kw + kw0 + c4);
            cpa16(sd + BUFB + o, Bw + (size_t)(bcol + r) * Kw + kw0 + c4);
        }
        asm volatile("cp.async.commit_group;");
    };

    issue(0, 0);
    issue(1, 32);

    for (int i = 0; i < nst; i++) {
        if (i + 2 < nst) {
            issue((i + 2) % 3, (i + 2) * 32);
            asm volatile("cp.async.wait_group 2;");
        } else if (i + 1 < nst) {
            asm volatile("cp.async.wait_group 1;");
        } else {
            asm volatile("cp.async.wait_group 0;");
        }
        __syncthreads();

        const unsigned sd = sb + (i % 3) * STAGEB;
        const unsigned sA = sd, sB = sd + BUFB;

#pragma unroll
        for (int ks2 = 0; ks2 < 32; ks2 += 8) {
            unsigned bh[4][2];
#pragma unroll
            for (int pr = 0; pr < 4; pr += 2) {
                int nrow = wc + (pr + (sub >> 1)) * 8 + r8;
                int colw = ks2 + (sub & 1) * 4;
                unsigned off = (unsigned)(nrow * GST + colw) * 4;
                ldsm4(bh[pr][0], bh[pr][1], bh[pr + 1][0], bh[pr + 1][1], sB + off);
            }
#pragma unroll
            for (int mt = 0; mt < 4; mt++) {
                int arow = wr + mt * 16 + (sub & 1) * 8 + r8;
                int colw = ks2 + (sub >> 1) * 4;
                unsigned off = (unsigned)(arow * GST + colw) * 4;
                unsigned ah[4];
                ldsm4(ah[0], ah[1], ah[2], ah[3], sA + off);
#pragma unroll
                for (int nt = 0; nt < 4; nt++)
                    mma16f(acc[mt][nt], ah, bh[nt]);
            }
        }
        __syncthreads();
    }

    if (Ch) {
        unsigned* Chw = (unsigned*)Ch;
        const int Ncw = Nc >> 1;
#pragma unroll
        for (int mt = 0; mt < 4; mt++) {
#pragma unroll
            for (int nt = 0; nt < 4; nt++) {
                int row = brow + wr + mt * 16 + l4;
                int col = bcol + wc + nt * 8 + 2 * q;
                float sc = (col < scaleCols) ? scaleVal : 1.0f;
                Chw[(size_t)row * Ncw + (col >> 1)] =
                    h2u(acc[mt][nt][0] * sc, acc[mt][nt][1] * sc);
                Chw[(size_t)(row + 8) * Ncw + (col >> 1)] =
                    h2u(acc[mt][nt][2] * sc, acc[mt][nt][3] * sc);
            }
        }
    } else {
#pragma unroll
        for (int mt = 0; mt < 4; mt++) {
#pragma unroll
            for (int nt = 0; nt < 4; nt++) {
                int row = brow + wr + mt * 16 + l4;
                int col = bcol + wc + nt * 8 + 2 * q;
                float b0 = 0.f, b1 = 0.f;
                if (bias) { b0 = bias[col]; b1 = bias[col + 1]; }
                *(float2*)(Cf + (size_t)row * Nc + col) =
                    make_float2(acc[mt][nt][0] + b0, acc[mt][nt][1] + b1);
                *(float2*)(Cf + (size_t)(row + 8) * Nc + col) =
                    make_float2(acc[mt][nt][2] + b0, acc[mt][nt][3] + b1);
            }
        }
    }
}

// ===================================================================
// Flash attention: FBM=128, FBN=64, 8 warps x 16 rows.
// cp.async 3-STAGE K/V pipeline. P in registers. ldsm K/V frags.
// l via ones-MMA. Rescale skipped when no new max. Heavy-first blocks.
// exp2 in fp32 (R16 showed f16x2 was neutral-speed, worse-precision).
// ===================================================================
#define FBM 128
#define FBN 64
#define KSW 36                        // K/V row stride (words)
#define KBUF (FBN * KSW * 4)          // 9216 B per K (or V) buffer
#define FSTAGE (2 * KBUF)             // 18432 B per stage (K+V)
#define FLASH_SMEMB (3 * FSTAGE)      // 55296 B

__global__ __launch_bounds__(256, 2)
void flash16(const __half* __restrict__ QKV16, __half* __restrict__ c16)
{
    extern __shared__ char fsm[];
    const unsigned sbd = smem_u32(fsm);

    const int tid  = threadIdx.x;
    const int lane = tid & 31;
    const int wid  = tid >> 5;              // 0..7
    const int q    = lane & 3;
    const int l4   = lane >> 2;
    const int sub  = lane >> 3;
    const int r8   = lane & 7;
    // heavy-first: reverse q-tile order so long blocks start in wave 1
    const int m0   = (gridDim.x - 1 - blockIdx.x) * FBM;
    const int h    = blockIdx.y;
    const int b    = blockIdx.z;
    const int kv   = h >> 2;

    const int r0 = m0 + wid * 16 + l4;
    const int rowmin = m0 + wid * 16;
    const unsigned* W = (const unsigned*)QKV16;   // word ptr, row stride 1536

    // Q fragments (qscale pre-folded in gemm epilogue)
    unsigned qh[4][4];
    {
        size_t q0 = (size_t)(b * N_ + r0) * 1536 + h * 32;
        size_t q1 = q0 + (size_t)8 * 1536;
#pragma unroll
        for (int ks = 0; ks < 4; ks++) {
            qh[ks][0] = W[q0 + ks * 8 + q];
            qh[ks][1] = W[q1 + ks * 8 + q];
            qh[ks][2] = W[q0 + ks * 8 + q + 4];
            qh[ks][3] = W[q1 + ks * 8 + q + 4];
        }
    }

    float oacc[8][4];
#pragma unroll
    for (int d = 0; d < 8; d++)
#pragma unroll
        for (int e = 0; e < 4; e++) oacc[d][e] = 0.0f;
    float lacc[4] = {0.f, 0.f, 0.f, 0.f};       // row-sum C-frag (ones-MMA)
    float mcur0 = -1e30f, mcur1 = -1e30f;

    const unsigned ones2[2] = {0x3C003C00u, 0x3C003C00u};   // half2(1,1) x2

    const int rowmax = rowmin + 15;
    const int ntiles = (m0 + FBM) / FBN;        // >= 2 always

    auto fissue = [&](int stage, int n0) {
        unsigned sd = sbd + stage * FSTAGE;
#pragma unroll
        for (int p = 0; p < 2; p++) {
            int id = tid + p * 256;
            int r  = id >> 3;
            int w4 = (id & 7) * 4;
            size_t rowbase = (size_t)(b * N_ + n0 + r) * 1536 + kv * 32;
            unsigned o = (unsigned)(r * KSW + w4) * 4;
            cpa16(sd + o,        W + rowbase + 1024 + w4);   // K
            cpa16(sd + KBUF + o, W + rowbase + 1280 + w4);   // V
        }
        asm volatile("cp.async.commit_group;");
    };

    fissue(0, 0);
    fissue(1, FBN);

    for (int i = 0; i < ntiles; i++) {
        const int n0 = i * FBN;
        if (i + 2 < ntiles) {
            fissue((i + 2) % 3, (i + 2) * FBN);
            asm volatile("cp.async.wait_group 2;");
        } else if (i + 1 < ntiles) {
            asm volatile("cp.async.wait_group 1;");
        } else {
            asm volatile("cp.async.wait_group 0;");
        }
        __syncthreads();

        const unsigned sbK = sbd + (i % 3) * FSTAGE;
        const unsigned sbV = sbK + KBUF;

        if (n0 <= rowmax) {
            // ---- S = Q K^T : 4 k16 steps x 8 n-subtiles; ldsm interleaved ----
            float s[8][4];
#pragma unroll
            for (int nt = 0; nt < 8; nt++)
#pragma unroll
                for (int e = 0; e < 4; e++) s[nt][e] = 0.0f;

#pragma unroll
            for (int ks = 0; ks < 4; ks++) {
                const int colw = ks * 8 + (sub & 1) * 4;
#pragma unroll
                for (int pr = 0; pr < 8; pr += 2) {
                    int nrow = (pr + (sub >> 1)) * 8 + r8;
                    unsigned off = (unsigned)(nrow * KSW + colw) * 4;
                    unsigned b0[2], b1[2];
                    ldsm4(b0[0], b0[1], b1[0], b1[1], sbK + off);
                    mma16f(s[pr],     qh[ks], b0);
                    mma16f(s[pr + 1], qh[ks], b1);
                }
            }

            // ---- row max (mask only on diagonal tiles) ----
            float mt0 = -1e30f, mt1 = -1e30f;
            if (n0 + FBN - 1 > rowmin) {
#pragma unroll
                for (int nt = 0; nt < 8; nt++) {
#pragma unroll
                    for (int e = 0; e < 2; e++) {
                        int col = n0 + nt * 8 + 2 * q + e;
                        if (col > r0)     s[nt][e]     = -1e30f;
                        if (col > r0 + 8) s[nt][2 + e] = -1e30f;
                        mt0 = fmaxf(mt0, s[nt][e]);
                        mt1 = fmaxf(mt1, s[nt][2 + e]);
                    }
                }
            } else {
#pragma unroll
                for (int nt = 0; nt < 8; nt++) {
                    mt0 = fmaxf(mt0, fmaxf(s[nt][0], s[nt][1]));
                    mt1 = fmaxf(mt1, fmaxf(s[nt][2], s[nt][3]));
                }
            }
            mt0 = fmaxf(mt0, __shfl_xor_sync(0xffffffff, mt0, 1));
            mt0 = fmaxf(mt0, __shfl_xor_sync(0xffffffff, mt0, 2));
            mt1 = fmaxf(mt1, __shfl_xor_sync(0xffffffff, mt1, 1));
            mt1 = fmaxf(mt1, __shfl_xor_sync(0xffffffff, mt1, 2));

            float mn0 = fmaxf(mcur0, mt0);
            float mn1 = fmaxf(mcur1, mt1);
            // skip rescale when no lane saw a new max (cr==1 exactly)
            unsigned need = __ballot_sync(0xffffffff, (mn0 > mcur0) || (mn1 > mcur1));
            if (need) {
                float cr0 = ex2(mcur0 - mn0);
                float cr1 = ex2(mcur1 - mn1);
#pragma unroll
                for (int d = 0; d < 8; d++) {
                    oacc[d][0] *= cr0; oacc[d][1] *= cr0;
                    oacc[d][2] *= cr1; oacc[d][3] *= cr1;
                }
                lacc[0] *= cr0; lacc[1] *= cr0;
                lacc[2] *= cr1; lacc[3] *= cr1;
            }
            mcur0 = mn0; mcur1 = mn1;

            // ---- P in registers: C-frag -> A-frag layout ----
            unsigned pa[8][2];
#pragma unroll
            for (int nt = 0; nt < 8; nt++) {
                pa[nt][0] = h2u(ex2(s[nt][0] - mn0), ex2(s[nt][1] - mn0));
                pa[nt][1] = h2u(ex2(s[nt][2] - mn1), ex2(s[nt][3] - mn1));
            }

            // ---- O += P V ; l += P 1 : 4 k16 steps ----
#pragma unroll
            for (int ks = 0; ks < 4; ks++) {
                unsigned a[4];
                a[0] = pa[2 * ks][0];
                a[1] = pa[2 * ks][1];
                a[2] = pa[2 * ks + 1][0];
                a[3] = pa[2 * ks + 1][1];
                mma16f(lacc, a, ones2);                   // row sums
                int vrow = ks * 16 + (sub & 1) * 8 + r8;
#pragma unroll
                for (int dtp = 0; dtp < 4; dtp++) {
                    unsigned v0, v1, v2, v3;
                    unsigned addr = sbV + (unsigned)(vrow * (KSW * 4))
                                  + (unsigned)((dtp * 16 + (sub >> 1) * 8) * 2);
                    ldsm4t(v0, v1, v2, v3, addr);
                    unsigned b0[2] = {v0, v1};
                    unsigned b1[2] = {v2, v3};
                    mma16f(oacc[2 * dtp],     a, b0);
                    mma16f(oacc[2 * dtp + 1], a, b1);
                }
            }
        }
        __syncthreads();
    }

    // lacc columns are identical row sums — no reduction needed
    float inv0 = 1.0f / lacc[0];
    float inv1 = 1.0f / lacc[2];

    unsigned* cw = (unsigned*)c16;
    size_t c0 = (size_t)(b * N_ + r0) * 1024 + h * 32;
    size_t c1 = c0 + (size_t)8 * 1024;
#pragma unroll
    for (int dt = 0; dt < 8; dt++) {
        cw[c0 + dt * 4 + q] = h2u(oacc[dt][0] * inv0, oacc[dt][1] * inv0);
        cw[c1 + dt * 4 + q] = h2u(oacc[dt][2] * inv1, oacc[dt][3] * inv1);
    }
}

// ===================================================================
// Launch
// ===================================================================
extern "C" void kernel_launch(void* const* d_in, const int* in_sizes, int n_in,
                              void* d_out, int out_size)
{
    const float* x  = (const float*)d_in[0];
    const float* Wq = (const float*)d_in[1];
    const float* Wk = (const float*)d_in[2];
    const float* Wv = (const float*)d_in[3];
    const float* Wo = (const float*)d_in[4];
    const float* bo = (const float*)d_in[5];
    float* out = (float*)d_out;

    __half *x16, *Wqkv16, *Wo16, *QKV16, *c16;
    cudaGetSymbolAddress((void**)&x16,    g_x16);
    cudaGetSymbolAddress((void**)&Wqkv16, g_Wqkv16);
    cudaGetSymbolAddress((void**)&Wo16,   g_Wo16);
    cudaGetSymbolAddress((void**)&QKV16,  g_QKV16);
    cudaGetSymbolAddress((void**)&c16,    g_c16);

    cudaFuncSetAttribute(gemm_f16, cudaFuncAttributeMaxDynamicSharedMemorySize,
                         GEMM_SMEMB);
    cudaFuncSetAttribute(flash16, cudaFuncAttributeMaxDynamicSharedMemorySize,
                         FLASH_SMEMB);

    const float qscale = 0.125f * 1.44269504f;

    // input conversions (weights transpose + x convert, one launch)
    conv_all<<<10240 + 8192, 256>>>(x, Wq, Wk, Wv, Wo, x16, Wqkv16, Wo16);

    // fused QKV projection -> fp16 (Q columns pre-scaled by qscale)
    gemm_f16<<<dim3(QKVW / 128, M_ / 128), 256, GEMM_SMEMB>>>(
        x16, Wqkv16, nullptr, QKV16, nullptr, QKVW, DIN, 2048, qscale);

    // attention
    flash16<<<dim3(N_ / FBM, H_, B_), 256, FLASH_SMEMB>>>(QKV16, c16);

    // output projection + bias -> fp32 out
    gemm_f16<<<dim3(DIN / 128, M_ / 128), 256, GEMM_SMEMB>>>(
        c16, Wo16, out, nullptr, bo, DIN, DOUT, 0, 1.0f);
}